// round 14
// baseline (speedup 1.0000x reference)
#include <cuda_runtime.h>
#include <cuda_bf16.h>
#include <stdint.h>

#define N_NODES 50000
#define N_EDGES 800000
#define C_IN    256
#define C_HID   128
#define C_OUT   64

#define SCAN_TB 256
#define SCAN_NB ((N_NODES + SCAN_TB - 1) / SCAN_TB)   // 196

// ---------------- scratch (static device globals; no allocation) ----------------
// RULE (learned R1/R7): never pass these as kernel arguments from host code.
// RULE (learned R12): tcgen05 is NOT compilable in this harness (PTX targets
// compute_103 without the 'a' feature set) — mma.sync is the tensor path.
__device__ int   g_is64;
__device__ int   g_cnt[N_NODES];
__device__ float g_dinv[N_NODES];
__device__ int   g_rowptr[N_NODES + 1];
__device__ int   g_fill[N_NODES];
__device__ int   g_srcidx[N_EDGES];
__device__ float g_norm[N_EDGES];
__device__ int   g_bsum[SCAN_NB];
__device__ int   g_boff[SCAN_NB];
__device__ float g_h1[(size_t)N_NODES * C_HID];
__device__ float g_h2[(size_t)N_NODES * C_OUT];
__device__ uint32_t g_a1h[(size_t)N_NODES * (C_HID / 2)];
__device__ uint32_t g_a1l[(size_t)N_NODES * (C_HID / 2)];
__device__ uint32_t g_w1h[C_HID * (C_IN / 2)];
__device__ uint32_t g_w1l[C_HID * (C_IN / 2)];
__device__ uint32_t g_w2h[C_OUT * (C_HID / 2)];
__device__ uint32_t g_w2l[C_OUT * (C_HID / 2)];

// ---------------- helpers ----------------
__device__ __forceinline__ uint32_t packbf2(float x, float y) {
    __nv_bfloat162 v = __floats2bfloat162_rn(x, y);
    return *(uint32_t*)&v;
}
__device__ __forceinline__ void split2(float x, float y, uint32_t& hi, uint32_t& lo) {
    __nv_bfloat16 hx = __float2bfloat16_rn(x);
    __nv_bfloat16 hy = __float2bfloat16_rn(y);
    __nv_bfloat162 h = __halves2bfloat162(hx, hy);
    hi = *(uint32_t*)&h;
    lo = packbf2(x - __bfloat162float(hx), y - __bfloat162float(hy));
}

#define MMA_BF16(c, a, b)                                                     \
    asm volatile(                                                             \
        "mma.sync.aligned.m16n8k16.row.col.f32.bf16.bf16.f32 "                \
        "{%0,%1,%2,%3},{%4,%5,%6,%7},{%8,%9},{%0,%1,%2,%3};"                  \
        : "+f"((c)[0]), "+f"((c)[1]), "+f"((c)[2]), "+f"((c)[3])              \
        : "r"((a)[0]), "r"((a)[1]), "r"((a)[2]), "r"((a)[3]),                 \
          "r"((b)[0]), "r"((b)[1]))

// ---------------- edge dtype detection ----------------
__global__ void detect_dtype_kernel(const void* ei) {
    const long long* e64 = (const long long*)ei;
    bool ok = true;
    for (int i = 0; i < 8; i++) {
        long long s = e64[i];
        long long d = e64[N_EDGES + i];
        if (s < 0 || s >= N_NODES || d < 0 || d >= N_NODES) ok = false;
    }
    g_is64 = ok ? 1 : 0;
}

__device__ __forceinline__ int edge_at(const void* ei, size_t idx, int is64) {
    long long v;
    if (is64) v = ((const long long*)ei)[idx];
    else      v = (long long)((const int*)ei)[idx];
    v = v < 0 ? 0 : (v >= N_NODES ? N_NODES - 1 : v);
    return (int)v;
}

// ---------------- weight prep ----------------
template <int LAYER>
__global__ void wprep_kernel(const float* __restrict__ W) {
    constexpr int K = (LAYER == 0) ? C_IN  : C_HID;
    constexpr int N = (LAYER == 0) ? C_HID : C_OUT;
    uint32_t* __restrict__ Wh = (LAYER == 0) ? g_w1h : g_w2h;
    uint32_t* __restrict__ Wl = (LAYER == 0) ? g_w1l : g_w2l;
    int idx = blockIdx.x * blockDim.x + threadIdx.x;
    if (idx >= N * (K / 2)) return;
    int n  = idx / (K / 2);
    int kp = idx % (K / 2);
    float f0 = W[(size_t)(2 * kp) * N + n];
    float f1 = W[(size_t)(2 * kp + 1) * N + n];
    uint32_t hi, lo;
    split2(f0, f1, hi, lo);
    Wh[idx] = hi;
    Wl[idx] = lo;
}

// ---------------- CSR build ----------------
__global__ void zero_cnt_kernel() {
    int i = blockIdx.x * blockDim.x + threadIdx.x;
    if (i < N_NODES) g_cnt[i] = 0;
}

__global__ void count_kernel(const void* __restrict__ ei) {
    int e = blockIdx.x * blockDim.x + threadIdx.x;
    if (e < N_EDGES) {
        int d = edge_at(ei, (size_t)N_EDGES + e, g_is64);
        atomicAdd(&g_cnt[d], 1);
    }
}

__global__ void dinv_kernel() {
    int i = blockIdx.x * blockDim.x + threadIdx.x;
    if (i < N_NODES) {
        float deg = (float)g_cnt[i] + 1.0f;
        g_dinv[i] = rsqrtf(deg);
    }
}

__global__ void scan1_kernel() {
    __shared__ int sm[SCAN_TB];
    int i = blockIdx.x * SCAN_TB + threadIdx.x;
    sm[threadIdx.x] = (i < N_NODES) ? g_cnt[i] : 0;
    __syncthreads();
#pragma unroll
    for (int off = SCAN_TB / 2; off > 0; off >>= 1) {
        if (threadIdx.x < off) sm[threadIdx.x] += sm[threadIdx.x + off];
        __syncthreads();
    }
    if (threadIdx.x == 0) g_bsum[blockIdx.x] = sm[0];
}

__global__ void scan2_kernel() {
    __shared__ int sm[SCAN_TB];
    int tid = threadIdx.x;
    sm[tid] = (tid < SCAN_NB) ? g_bsum[tid] : 0;
    __syncthreads();
#pragma unroll
    for (int off = 1; off < SCAN_TB; off <<= 1) {
        int v = 0;
        if (tid >= off) v = sm[tid - off];
        __syncthreads();
        if (tid >= off) sm[tid] += v;
        __syncthreads();
    }
    if (tid < SCAN_NB) g_boff[tid] = (tid == 0) ? 0 : sm[tid - 1];
}

__global__ void scan3_kernel() {
    __shared__ int sm[SCAN_TB];
    int tid = threadIdx.x;
    int i = blockIdx.x * SCAN_TB + tid;
    sm[tid] = (i < N_NODES) ? g_cnt[i] : 0;
    __syncthreads();
#pragma unroll
    for (int off = 1; off < SCAN_TB; off <<= 1) {
        int v = 0;
        if (tid >= off) v = sm[tid - off];
        __syncthreads();
        if (tid >= off) sm[tid] += v;
        __syncthreads();
    }
    if (i < N_NODES) {
        int excl = ((tid == 0) ? 0 : sm[tid - 1]) + g_boff[blockIdx.x];
        g_rowptr[i] = excl;
        g_fill[i]   = excl;
    }
    if (blockIdx.x == 0 && tid == 0) g_rowptr[N_NODES] = N_EDGES;
}

__global__ void scatter_kernel(const void* __restrict__ ei) {
    int e = blockIdx.x * blockDim.x + threadIdx.x;
    if (e < N_EDGES) {
        int is64 = g_is64;
        int s = edge_at(ei, e, is64);
        int d = edge_at(ei, (size_t)N_EDGES + e, is64);
        int p = atomicAdd(&g_fill[d], 1);
        g_srcidx[p] = s;
        g_norm[p]   = g_dinv[s] * g_dinv[d];
    }
}

// ---------------- bf16x3 tensor-core GEMM, double-buffered pipeline ----------------
template <int BM, int BN, int WARPS_M, int WARPS_N, int NN, int KK, int LAYER>
__global__ void __launch_bounds__(256)
mma_gemm_kernel(const float* __restrict__ A_ext, int M) {
    constexpr int BK  = 32;
    constexpr int KP  = BK / 2;
    constexpr int KPP = KP + 4;
    constexpr int WM = BM / WARPS_M, WN = BN / WARPS_N;
    constexpr int MI = WM / 16, NI = WN / 8;
    constexpr int ALD0 = BM * (BK / 4) / 256;
    constexpr int ALD1 = BM * KP / 256;
    constexpr int BLD  = BN * KP / 256;
    constexpr int ASZ = BM * KPP;
    constexpr int BSZ = BN * KPP;

    extern __shared__ uint32_t smp[];
    uint32_t* Ah = smp;
    uint32_t* Al = Ah + 2 * ASZ;
    uint32_t* Bh = Al + 2 * ASZ;
    uint32_t* Bl = Bh + 2 * BSZ;

    const uint32_t* __restrict__ WhG = (LAYER == 0) ? g_w1h : g_w2h;
    const uint32_t* __restrict__ WlG = (LAYER == 0) ? g_w1l : g_w2l;
    float* __restrict__ C = (LAYER == 0) ? (float*)g_h1 : (float*)g_h2;

    const int tid  = threadIdx.x;
    const int wid  = tid >> 5;
    const int lane = tid & 31;
    const int g    = lane >> 2;
    const int t    = lane & 3;
    const int wm   = (wid / WARPS_N) * WM;
    const int wn   = (wid % WARPS_N) * WN;
    const int block_m = blockIdx.x * BM;

    float4   ra0[ALD0 > 0 ? ALD0 : 1];
    uint32_t ra1h[ALD1], ra1l[ALD1];
    uint32_t rbh[BLD], rbl[BLD];

    float acc[MI][NI][4];
#pragma unroll
    for (int mi = 0; mi < MI; mi++)
#pragma unroll
        for (int ni = 0; ni < NI; ni++)
#pragma unroll
            for (int j = 0; j < 4; j++) acc[mi][ni][j] = 0.0f;

    auto load_tile = [&](int k0) {
        if (LAYER == 0) {
#pragma unroll
            for (int u = 0; u < ALD0; u++) {
                int i = u * 256 + tid;
                int row = i / (BK / 4);
                int c4  = i % (BK / 4);
                int gm  = block_m + row;
                ra0[u] = (gm < M) ? *(const float4*)&A_ext[(size_t)gm * KK + k0 + c4 * 4]
                                  : make_float4(0.f, 0.f, 0.f, 0.f);
            }
        } else {
#pragma unroll
            for (int u = 0; u < ALD1; u++) {
                int i = u * 256 + tid;
                int row = i / KP;
                int kp  = i % KP;
                int gm  = block_m + row;
                ra1h[u] = (gm < M) ? g_a1h[(size_t)gm * (KK / 2) + k0 / 2 + kp] : 0;
                ra1l[u] = (gm < M) ? g_a1l[(size_t)gm * (KK / 2) + k0 / 2 + kp] : 0;
            }
        }
#pragma unroll
        for (int u = 0; u < BLD; u++) {
            int i = u * 256 + tid;
            int n  = i / KP;
            int kp = i % KP;
            rbh[u] = WhG[(size_t)n * (KK / 2) + k0 / 2 + kp];
            rbl[u] = WlG[(size_t)n * (KK / 2) + k0 / 2 + kp];
        }
    };

    auto store_tile = [&](int st) {
        uint32_t* ah = Ah + st * ASZ;
        uint32_t* al = Al + st * ASZ;
        uint32_t* bh = Bh + st * BSZ;
        uint32_t* bl = Bl + st * BSZ;
        if (LAYER == 0) {
#pragma unroll
            for (int u = 0; u < ALD0; u++) {
                int i = u * 256 + tid;
                int row = i / (BK / 4);
                int c4  = i % (BK / 4);
                uint32_t h0, l0, h1, l1;
                split2(ra0[u].x, ra0[u].y, h0, l0);
                split2(ra0[u].z, ra0[u].w, h1, l1);
                ah[row * KPP + c4 * 2 + 0] = h0;
                ah[row * KPP + c4 * 2 + 1] = h1;
                al[row * KPP + c4 * 2 + 0] = l0;
                al[row * KPP + c4 * 2 + 1] = l1;
            }
        } else {
#pragma unroll
            for (int u = 0; u < ALD1; u++) {
                int i = u * 256 + tid;
                int row = i / KP;
                int kp  = i % KP;
                ah[row * KPP + kp] = ra1h[u];
                al[row * KPP + kp] = ra1l[u];
            }
        }
#pragma unroll
        for (int u = 0; u < BLD; u++) {
            int i = u * 256 + tid;
            int n  = i / KP;
            int kp = i % KP;
            bh[n * KPP + kp] = rbh[u];
            bl[n * KPP + kp] = rbl[u];
        }
    };

    auto compute = [&](int st) {
        const uint32_t* ahp = Ah + st * ASZ;
        const uint32_t* alp = Al + st * ASZ;
        const uint32_t* bhp = Bh + st * BSZ;
        const uint32_t* blp = Bl + st * BSZ;
#pragma unroll
        for (int s = 0; s < 2; s++) {
            const int sp = s * 8;
            uint32_t ah[MI][4], al[MI][4];
#pragma unroll
            for (int mi = 0; mi < MI; mi++) {
                int r = wm + mi * 16;
                ah[mi][0] = ahp[(r + g) * KPP + sp + t];
                ah[mi][1] = ahp[(r + g + 8) * KPP + sp + t];
                ah[mi][2] = ahp[(r + g) * KPP + sp + t + 4];
                ah[mi][3] = ahp[(r + g + 8) * KPP + sp + t + 4];
                al[mi][0] = alp[(r + g) * KPP + sp + t];
                al[mi][1] = alp[(r + g + 8) * KPP + sp + t];
                al[mi][2] = alp[(r + g) * KPP + sp + t + 4];
                al[mi][3] = alp[(r + g + 8) * KPP + sp + t + 4];
            }
            uint32_t bh[NI][2], bl[NI][2];
#pragma unroll
            for (int ni = 0; ni < NI; ni++) {
                int n = wn + ni * 8 + g;
                bh[ni][0] = bhp[n * KPP + sp + t];
                bh[ni][1] = bhp[n * KPP + sp + t + 4];
                bl[ni][0] = blp[n * KPP + sp + t];
                bl[ni][1] = blp[n * KPP + sp + t + 4];
            }
#pragma unroll
            for (int mi = 0; mi < MI; mi++)
#pragma unroll
                for (int ni = 0; ni < NI; ni++) {
                    MMA_BF16(acc[mi][ni], ah[mi], bh[ni]);
                    MMA_BF16(acc[mi][ni], ah[mi], bl[ni]);
                    MMA_BF16(acc[mi][ni], al[mi], bh[ni]);
                }
        }
    };

    int st = 0;
    load_tile(0);
    store_tile(st);
    __syncthreads();
    for (int k0 = 0; k0 < KK; k0 += BK) {
        const bool has_next = (k0 + BK < KK);
        if (has_next) load_tile(k0 + BK);
        compute(st);
        if (has_next) {
            store_tile(st ^ 1);
            __syncthreads();
            st ^= 1;
        }
    }

#pragma unroll
    for (int mi = 0; mi < MI; mi++) {
#pragma unroll
        for (int ni = 0; ni < NI; ni++) {
            int r0 = block_m + wm + mi * 16 + g;
            int c0 = wn + ni * 8 + 2 * t;
            if (r0 < M)
                *(float2*)&C[(size_t)r0 * NN + c0] =
                    make_float2(acc[mi][ni][0], acc[mi][ni][1]);
            if (r0 + 8 < M)
                *(float2*)&C[(size_t)(r0 + 8) * NN + c0] =
                    make_float2(acc[mi][ni][2], acc[mi][ni][3]);
        }
    }
}

// ---------------- aggregation (one warp per dst node, 8-wide gather pipeline) ----------------
__global__ void agg128_relu_kernel(const float* __restrict__ bias) {
    const float* __restrict__ h = (const float*)g_h1;
    const int warp = blockIdx.x * (blockDim.x >> 5) + (threadIdx.x >> 5);
    const int lane = threadIdx.x & 31;
    if (warp >= N_NODES) return;

    const int start = g_rowptr[warp];
    const int end   = g_rowptr[warp + 1];

    float4 acc = make_float4(0.f, 0.f, 0.f, 0.f);
    for (int base = start; base < end; base += 32) {
        int e = base + lane;
        int s = 0; float nm = 0.f;
        if (e < end) { s = g_srcidx[e]; nm = g_norm[e]; }
        int cnt = min(32, end - base);
        int j = 0;
        for (; j + 8 <= cnt; j += 8) {
            int sv[8]; float nv[8]; float4 vv[8];
#pragma unroll
            for (int u = 0; u < 8; u++) {
                sv[u] = __shfl_sync(0xffffffffu, s, j + u);
                nv[u] = __shfl_sync(0xffffffffu, nm, j + u);
            }
#pragma unroll
            for (int u = 0; u < 8; u++)
                vv[u] = *(const float4*)&h[(size_t)sv[u] * C_HID + lane * 4];
#pragma unroll
            for (int u = 0; u < 8; u++) {
                acc.x += vv[u].x * nv[u];
                acc.y += vv[u].y * nv[u];
                acc.z += vv[u].z * nv[u];
                acc.w += vv[u].w * nv[u];
            }
        }
        for (; j < cnt; j++) {
            int   ss = __shfl_sync(0xffffffffu, s, j);
            float nn = __shfl_sync(0xffffffffu, nm, j);
            float4 v = *(const float4*)&h[(size_t)ss * C_HID + lane * 4];
            acc.x += v.x * nn; acc.y += v.y * nn;
            acc.z += v.z * nn; acc.w += v.w * nn;
        }
    }
    float dv = g_dinv[warp];
    float sn = dv * dv;
    float4 v = *(const float4*)&h[(size_t)warp * C_HID + lane * 4];
    acc.x += v.x * sn; acc.y += v.y * sn; acc.z += v.z * sn; acc.w += v.w * sn;
    const float4 b = *(const float4*)&bias[lane * 4];
    acc.x = fmaxf(acc.x + b.x, 0.f);
    acc.y = fmaxf(acc.y + b.y, 0.f);
    acc.z = fmaxf(acc.z + b.z, 0.f);
    acc.w = fmaxf(acc.w + b.w, 0.f);
    uint32_t h0, l0, h1, l1;
    split2(acc.x, acc.y, h0, l0);
    split2(acc.z, acc.w, h1, l1);
    size_t o = (size_t)warp * (C_HID / 2) + lane * 2;
    g_a1h[o]     = h0;
    g_a1h[o + 1] = h1;
    g_a1l[o]     = l0;
    g_a1l[o + 1] = l1;
}

__global__ void agg64_kernel(const float* __restrict__ bias,
                             float* __restrict__ out) {
    const float* __restrict__ h = (const float*)g_h2;
    const int warp = blockIdx.x * (blockDim.x >> 5) + (threadIdx.x >> 5);
    const int lane = threadIdx.x & 31;
    if (warp >= N_NODES) return;

    const int start = g_rowptr[warp];
    const int end   = g_rowptr[warp + 1];

    float2 acc = make_float2(0.f, 0.f);
    for (int base = start; base < end; base += 32) {
        int e = base + lane;
        int s = 0; float nm = 0.f;
        if (e < end) { s = g_srcidx[e]; nm = g_norm[e]; }
        int cnt = min(32, end - base);
        int j = 0;
        for (; j + 8 <= cnt; j += 8) {
            int sv[8]; float nv[8]; float2 vv[8];
#pragma unroll
            for (int u = 0; u < 8; u++) {
                sv[u] = __shfl_sync(0xffffffffu, s, j + u);
                nv[u] = __shfl_sync(0xffffffffu, nm, j + u);
            }
#pragma unroll
            for (int u = 0; u < 8; u++)
                vv[u] = *(const float2*)&h[(size_t)sv[u] * C_OUT + lane * 2];
#pragma unroll
            for (int u = 0; u < 8; u++) {
                acc.x += vv[u].x * nv[u];
                acc.y += vv[u].y * nv[u];
            }
        }
        for (; j < cnt; j++) {
            int   ss = __shfl_sync(0xffffffffu, s, j);
            float nn = __shfl_sync(0xffffffffu, nm, j);
            float2 v = *(const float2*)&h[(size_t)ss * C_OUT + lane * 2];
            acc.x += v.x * nn; acc.y += v.y * nn;
        }
    }
    float dv = g_dinv[warp];
    float sn = dv * dv;
    float2 v = *(const float2*)&h[(size_t)warp * C_OUT + lane * 2];
    acc.x += v.x * sn; acc.y += v.y * sn;
    const float2 b = *(const float2*)&bias[lane * 2];
    acc.x += b.x; acc.y += b.y;
    *(float2*)&out[(size_t)warp * C_OUT + lane * 2] = acc;
}

// ---------------- launch (fork-join: CSR build overlaps layer-1 GEMM) ----------------
extern "C" void kernel_launch(void* const* d_in, const int* in_sizes, int n_in,
                              void* d_out, int out_size) {
    const float* x  = (const float*)d_in[0];
    const void*  ei = d_in[1];
    const float* W1 = (const float*)d_in[2];
    const float* b1 = (const float*)d_in[3];
    const float* W2 = (const float*)d_in[4];
    const float* b2 = (const float*)d_in[5];
    float* out = (float*)d_out;

    const int TB = 256;
    const int nodeBlocks = (N_NODES + TB - 1) / TB;
    const int edgeBlocks = (N_EDGES + TB - 1) / TB;

    cudaStream_t s2;
    cudaStreamCreate(&s2);
    cudaEvent_t evFork, evJoin;
    cudaEventCreateWithFlags(&evFork, cudaEventDisableTiming);
    cudaEventCreateWithFlags(&evJoin, cudaEventDisableTiming);

    // common prefix on the capture stream
    detect_dtype_kernel<<<1, 1>>>(ei);

    // fork: CSR build on s2 (needs only edge_index + g_is64)
    cudaEventRecord(evFork, 0);
    cudaStreamWaitEvent(s2, evFork, 0);
    zero_cnt_kernel<<<nodeBlocks, TB, 0, s2>>>();
    count_kernel<<<edgeBlocks, TB, 0, s2>>>(ei);
    dinv_kernel<<<nodeBlocks, TB, 0, s2>>>();
    scan1_kernel<<<SCAN_NB, SCAN_TB, 0, s2>>>();
    scan2_kernel<<<1, SCAN_TB, 0, s2>>>();
    scan3_kernel<<<SCAN_NB, SCAN_TB, 0, s2>>>();
    scatter_kernel<<<edgeBlocks, TB, 0, s2>>>(ei);
    cudaEventRecord(evJoin, s2);

    // main branch: weight prep + layer-1 GEMM (needs only x, W1, W2)
    wprep_kernel<0><<<(C_HID * C_IN / 2 + TB - 1) / TB, TB>>>(W1);
    wprep_kernel<1><<<(C_OUT * C_HID / 2 + TB - 1) / TB, TB>>>(W2);
    {
        constexpr int BM = 64;
        constexpr int SMEM = 4 * 20 * (BM + 128) * 4;
        auto kfn = mma_gemm_kernel<BM, 128, 2, 4, C_HID, C_IN, 0>;
        cudaFuncSetAttribute(kfn, cudaFuncAttributeMaxDynamicSharedMemorySize, SMEM);
        int grid = (N_NODES + BM - 1) / BM;
        kfn<<<grid, 256, SMEM>>>(x, N_NODES);
    }

    // join: aggregation needs BOTH h1 and the CSR
    cudaStreamWaitEvent(0, evJoin, 0);

    {
        const int WPB = 8;
        int grid = (N_NODES + WPB - 1) / WPB;
        agg128_relu_kernel<<<grid, WPB * 32>>>(b1);
    }
    {
        constexpr int BM = 64;
        constexpr int SMEM = 4 * 20 * (BM + 64) * 4;
        auto kfn = mma_gemm_kernel<BM, 64, 2, 4, C_OUT, C_HID, 1>;
        cudaFuncSetAttribute(kfn, cudaFuncAttributeMaxDynamicSharedMemorySize, SMEM);
        int grid = (N_NODES + BM - 1) / BM;
        kfn<<<grid, 256, SMEM>>>(nullptr, N_NODES);
    }
    {
        const int WPB = 8;
        int grid = (N_NODES + WPB - 1) / WPB;
        agg64_kernel<<<grid, WPB * 32>>>(b2, out);
    }

    // s2 joined the origin stream above; safe to release handles
    cudaEventDestroy(evFork);
    cudaEventDestroy(evJoin);
    cudaStreamDestroy(s2);
}

// round 15
// speedup vs baseline: 1.3262x; 1.3262x over previous
#include <cuda_runtime.h>
#include <cuda_bf16.h>
#include <stdint.h>

#define N_NODES 50000
#define N_EDGES 800000
#define C_IN    256
#define C_HID   128
#define C_OUT   64

#define SCAN_TB 256
#define SCAN_NB ((N_NODES + SCAN_TB - 1) / SCAN_TB)   // 196

// ---------------- scratch (static device globals; no allocation) ----------------
// RULE (learned R1/R7): never pass these as kernel arguments from host code.
// RULE (learned R12): tcgen05 is NOT compilable in this harness (plain compute_103).
// RULE (learned R14): keep the launch sequence a single linear stream — fork/join
// streams inside kernel_launch cost more than the overlap they buy.
__device__ int   g_is64;
__device__ int   g_cnt[N_NODES];
__device__ float g_dinv[N_NODES];
__device__ int   g_rowptr[N_NODES + 1];
__device__ int   g_fill[N_NODES];
__device__ int   g_srcidx[N_EDGES];
__device__ float g_norm[N_EDGES];
__device__ int   g_bsum[SCAN_NB];
__device__ int   g_boff[SCAN_NB];
__device__ float g_h1[(size_t)N_NODES * C_HID];
__device__ float g_h2[(size_t)N_NODES * C_OUT];
__device__ uint32_t g_a1h[(size_t)N_NODES * (C_HID / 2)];
__device__ uint32_t g_a1l[(size_t)N_NODES * (C_HID / 2)];
__device__ uint32_t g_w1h[C_HID * (C_IN / 2)];
__device__ uint32_t g_w1l[C_HID * (C_IN / 2)];
__device__ uint32_t g_w2h[C_OUT * (C_HID / 2)];
__device__ uint32_t g_w2l[C_OUT * (C_HID / 2)];

// ---------------- helpers ----------------
__device__ __forceinline__ uint32_t packbf2(float x, float y) {
    __nv_bfloat162 v = __floats2bfloat162_rn(x, y);
    return *(uint32_t*)&v;
}
__device__ __forceinline__ void split2(float x, float y, uint32_t& hi, uint32_t& lo) {
    __nv_bfloat16 hx = __float2bfloat16_rn(x);
    __nv_bfloat16 hy = __float2bfloat16_rn(y);
    __nv_bfloat162 h = __halves2bfloat162(hx, hy);
    hi = *(uint32_t*)&h;
    lo = packbf2(x - __bfloat162float(hx), y - __bfloat162float(hy));
}
__device__ __forceinline__ uint32_t smem_u32(const void* p) {
    uint32_t a;
    asm("{ .reg .u64 t; cvta.to.shared.u64 t, %1; cvt.u32.u64 %0, t; }" : "=r"(a) : "l"(p));
    return a;
}
__device__ __forceinline__ void ldsm4(uint32_t& r0, uint32_t& r1, uint32_t& r2,
                                      uint32_t& r3, uint32_t addr) {
    asm volatile("ldmatrix.sync.aligned.m8n8.x4.shared.b16 {%0,%1,%2,%3}, [%4];"
                 : "=r"(r0), "=r"(r1), "=r"(r2), "=r"(r3) : "r"(addr));
}

#define MMA_BF16(c, a, b)                                                     \
    asm volatile(                                                             \
        "mma.sync.aligned.m16n8k16.row.col.f32.bf16.bf16.f32 "                \
        "{%0,%1,%2,%3},{%4,%5,%6,%7},{%8,%9},{%0,%1,%2,%3};"                  \
        : "+f"((c)[0]), "+f"((c)[1]), "+f"((c)[2]), "+f"((c)[3])              \
        : "r"((a)[0]), "r"((a)[1]), "r"((a)[2]), "r"((a)[3]),                 \
          "r"((b)[0]), "r"((b)[1]))

// ---------------- edge dtype detection ----------------
__global__ void detect_dtype_kernel(const void* ei) {
    const long long* e64 = (const long long*)ei;
    bool ok = true;
    for (int i = 0; i < 8; i++) {
        long long s = e64[i];
        long long d = e64[N_EDGES + i];
        if (s < 0 || s >= N_NODES || d < 0 || d >= N_NODES) ok = false;
    }
    g_is64 = ok ? 1 : 0;
}

__device__ __forceinline__ int edge_at(const void* ei, size_t idx, int is64) {
    long long v;
    if (is64) v = ((const long long*)ei)[idx];
    else      v = (long long)((const int*)ei)[idx];
    v = v < 0 ? 0 : (v >= N_NODES ? N_NODES - 1 : v);
    return (int)v;
}

// ---------------- weight prep ----------------
template <int LAYER>
__global__ void wprep_kernel(const float* __restrict__ W) {
    constexpr int K = (LAYER == 0) ? C_IN  : C_HID;
    constexpr int N = (LAYER == 0) ? C_HID : C_OUT;
    uint32_t* __restrict__ Wh = (LAYER == 0) ? g_w1h : g_w2h;
    uint32_t* __restrict__ Wl = (LAYER == 0) ? g_w1l : g_w2l;
    int idx = blockIdx.x * blockDim.x + threadIdx.x;
    if (idx >= N * (K / 2)) return;
    int n  = idx / (K / 2);
    int kp = idx % (K / 2);
    float f0 = W[(size_t)(2 * kp) * N + n];
    float f1 = W[(size_t)(2 * kp + 1) * N + n];
    uint32_t hi, lo;
    split2(f0, f1, hi, lo);
    Wh[idx] = hi;
    Wl[idx] = lo;
}

// ---------------- CSR build ----------------
__global__ void zero_cnt_kernel() {
    int i = blockIdx.x * blockDim.x + threadIdx.x;
    if (i < N_NODES) g_cnt[i] = 0;
}

__global__ void count_kernel(const void* __restrict__ ei) {
    int e = blockIdx.x * blockDim.x + threadIdx.x;
    if (e < N_EDGES) {
        int d = edge_at(ei, (size_t)N_EDGES + e, g_is64);
        atomicAdd(&g_cnt[d], 1);
    }
}

// scan1 also computes dinv (same dependency: final g_cnt)
__global__ void scan1_kernel() {
    __shared__ int sm[SCAN_TB];
    int i = blockIdx.x * SCAN_TB + threadIdx.x;
    int c = (i < N_NODES) ? g_cnt[i] : 0;
    sm[threadIdx.x] = c;
    if (i < N_NODES) g_dinv[i] = rsqrtf((float)c + 1.0f);
    __syncthreads();
#pragma unroll
    for (int off = SCAN_TB / 2; off > 0; off >>= 1) {
        if (threadIdx.x < off) sm[threadIdx.x] += sm[threadIdx.x + off];
        __syncthreads();
    }
    if (threadIdx.x == 0) g_bsum[blockIdx.x] = sm[0];
}

__global__ void scan2_kernel() {
    __shared__ int sm[SCAN_TB];
    int tid = threadIdx.x;
    sm[tid] = (tid < SCAN_NB) ? g_bsum[tid] : 0;
    __syncthreads();
#pragma unroll
    for (int off = 1; off < SCAN_TB; off <<= 1) {
        int v = 0;
        if (tid >= off) v = sm[tid - off];
        __syncthreads();
        if (tid >= off) sm[tid] += v;
        __syncthreads();
    }
    if (tid < SCAN_NB) g_boff[tid] = (tid == 0) ? 0 : sm[tid - 1];
}

__global__ void scan3_kernel() {
    __shared__ int sm[SCAN_TB];
    int tid = threadIdx.x;
    int i = blockIdx.x * SCAN_TB + tid;
    sm[tid] = (i < N_NODES) ? g_cnt[i] : 0;
    __syncthreads();
#pragma unroll
    for (int off = 1; off < SCAN_TB; off <<= 1) {
        int v = 0;
        if (tid >= off) v = sm[tid - off];
        __syncthreads();
        if (tid >= off) sm[tid] += v;
        __syncthreads();
    }
    if (i < N_NODES) {
        int excl = ((tid == 0) ? 0 : sm[tid - 1]) + g_boff[blockIdx.x];
        g_rowptr[i] = excl;
        g_fill[i]   = excl;
    }
    if (blockIdx.x == 0 && tid == 0) g_rowptr[N_NODES] = N_EDGES;
}

__global__ void scatter_kernel(const void* __restrict__ ei) {
    int e = blockIdx.x * blockDim.x + threadIdx.x;
    if (e < N_EDGES) {
        int is64 = g_is64;
        int s = edge_at(ei, e, is64);
        int d = edge_at(ei, (size_t)N_EDGES + e, is64);
        int p = atomicAdd(&g_fill[d], 1);
        g_srcidx[p] = s;
        g_norm[p]   = g_dinv[s] * g_dinv[d];
    }
}

// ---------------- bf16x3 tensor-core GEMM, double-buffered + ldmatrix ----------------
template <int BM, int BN, int WARPS_M, int WARPS_N, int NN, int KK, int LAYER>
__global__ void __launch_bounds__(256)
mma_gemm_kernel(const float* __restrict__ A_ext, int M) {
    constexpr int BK  = 32;
    constexpr int KP  = BK / 2;
    constexpr int KPP = KP + 4;       // 80B row stride: 8-row groups are bank-disjoint for LDSM
    constexpr int WM = BM / WARPS_M, WN = BN / WARPS_N;
    constexpr int MI = WM / 16, NI = WN / 8;
    static_assert(NI % 2 == 0, "NI must be even for paired B ldmatrix");
    constexpr int ALD0 = BM * (BK / 4) / 256;
    constexpr int ALD1 = BM * KP / 256;
    constexpr int BLD  = BN * KP / 256;
    constexpr int ASZ = BM * KPP;
    constexpr int BSZ = BN * KPP;

    extern __shared__ uint32_t smp[];
    uint32_t* Ah = smp;
    uint32_t* Al = Ah + 2 * ASZ;
    uint32_t* Bh = Al + 2 * ASZ;
    uint32_t* Bl = Bh + 2 * BSZ;

    const uint32_t sm_base = smem_u32(smp);

    const uint32_t* __restrict__ WhG = (LAYER == 0) ? g_w1h : g_w2h;
    const uint32_t* __restrict__ WlG = (LAYER == 0) ? g_w1l : g_w2l;
    float* __restrict__ C = (LAYER == 0) ? (float*)g_h1 : (float*)g_h2;

    const int tid  = threadIdx.x;
    const int wid  = tid >> 5;
    const int lane = tid & 31;
    const int g    = lane >> 2;
    const int t    = lane & 3;
    const int wm   = (wid / WARPS_N) * WM;
    const int wn   = (wid % WARPS_N) * WN;
    const int block_m = blockIdx.x * BM;

    float4   ra0[ALD0 > 0 ? ALD0 : 1];
    uint32_t ra1h[ALD1], ra1l[ALD1];
    uint32_t rbh[BLD], rbl[BLD];

    float acc[MI][NI][4];
#pragma unroll
    for (int mi = 0; mi < MI; mi++)
#pragma unroll
        for (int ni = 0; ni < NI; ni++)
#pragma unroll
            for (int j = 0; j < 4; j++) acc[mi][ni][j] = 0.0f;

    auto load_tile = [&](int k0) {
        if (LAYER == 0) {
#pragma unroll
            for (int u = 0; u < ALD0; u++) {
                int i = u * 256 + tid;
                int row = i / (BK / 4);
                int c4  = i % (BK / 4);
                int gm  = block_m + row;
                ra0[u] = (gm < M) ? *(const float4*)&A_ext[(size_t)gm * KK + k0 + c4 * 4]
                                  : make_float4(0.f, 0.f, 0.f, 0.f);
            }
        } else {
#pragma unroll
            for (int u = 0; u < ALD1; u++) {
                int i = u * 256 + tid;
                int row = i / KP;
                int kp  = i % KP;
                int gm  = block_m + row;
                ra1h[u] = (gm < M) ? g_a1h[(size_t)gm * (KK / 2) + k0 / 2 + kp] : 0;
                ra1l[u] = (gm < M) ? g_a1l[(size_t)gm * (KK / 2) + k0 / 2 + kp] : 0;
            }
        }
#pragma unroll
        for (int u = 0; u < BLD; u++) {
            int i = u * 256 + tid;
            int n  = i / KP;
            int kp = i % KP;
            rbh[u] = WhG[(size_t)n * (KK / 2) + k0 / 2 + kp];
            rbl[u] = WlG[(size_t)n * (KK / 2) + k0 / 2 + kp];
        }
    };

    auto store_tile = [&](int st) {
        uint32_t* ah = Ah + st * ASZ;
        uint32_t* al = Al + st * ASZ;
        uint32_t* bh = Bh + st * BSZ;
        uint32_t* bl = Bl + st * BSZ;
        if (LAYER == 0) {
#pragma unroll
            for (int u = 0; u < ALD0; u++) {
                int i = u * 256 + tid;
                int row = i / (BK / 4);
                int c4  = i % (BK / 4);
                uint32_t h0, l0, h1, l1;
                split2(ra0[u].x, ra0[u].y, h0, l0);
                split2(ra0[u].z, ra0[u].w, h1, l1);
                ah[row * KPP + c4 * 2 + 0] = h0;
                ah[row * KPP + c4 * 2 + 1] = h1;
                al[row * KPP + c4 * 2 + 0] = l0;
                al[row * KPP + c4 * 2 + 1] = l1;
            }
        } else {
#pragma unroll
            for (int u = 0; u < ALD1; u++) {
                int i = u * 256 + tid;
                int row = i / KP;
                int kp  = i % KP;
                ah[row * KPP + kp] = ra1h[u];
                al[row * KPP + kp] = ra1l[u];
            }
        }
#pragma unroll
        for (int u = 0; u < BLD; u++) {
            int i = u * 256 + tid;
            int n  = i / KP;
            int kp = i % KP;
            bh[n * KPP + kp] = rbh[u];
            bl[n * KPP + kp] = rbl[u];
        }
    };

    auto compute = [&](int st) {
        const uint32_t baseAh = sm_base + (uint32_t)(st * ASZ) * 4u;
        const uint32_t baseAl = sm_base + (uint32_t)((2 + st) * ASZ) * 4u;
        const uint32_t baseBh = sm_base + (uint32_t)(4 * ASZ + st * BSZ) * 4u;
        const uint32_t baseBl = sm_base + (uint32_t)(4 * ASZ + (2 + st) * BSZ) * 4u;
        // per-thread ldmatrix row indices
        const int arow = lane & 15;            // A: row within 16-row frag
        const int ahalf = (lane >> 4) << 2;    // A: +4 u32 for k-high matrices
        const int q = lane >> 3;               // B: quad 0..3
        const int brow = lane & 7;             // B: row within 8-row frag
#pragma unroll
        for (int s = 0; s < 2; s++) {
            const int sp = s * 8;
            uint32_t ah[MI][4], al[MI][4];
#pragma unroll
            for (int mi = 0; mi < MI; mi++) {
                uint32_t offA = (uint32_t)((wm + mi * 16 + arow) * KPP + sp + ahalf) * 4u;
                ldsm4(ah[mi][0], ah[mi][1], ah[mi][2], ah[mi][3], baseAh + offA);
                ldsm4(al[mi][0], al[mi][1], al[mi][2], al[mi][3], baseAl + offA);
            }
            uint32_t bh[NI][2], bl[NI][2];
#pragma unroll
            for (int p = 0; p < NI / 2; p++) {
                uint32_t offB = (uint32_t)((wn + ((p << 1) + (q >> 1)) * 8 + brow) * KPP
                                           + sp + ((q & 1) << 2)) * 4u;
                ldsm4(bh[2 * p][0], bh[2 * p][1], bh[2 * p + 1][0], bh[2 * p + 1][1],
                      baseBh + offB);
                ldsm4(bl[2 * p][0], bl[2 * p][1], bl[2 * p + 1][0], bl[2 * p + 1][1],
                      baseBl + offB);
            }
#pragma unroll
            for (int mi = 0; mi < MI; mi++)
#pragma unroll
                for (int ni = 0; ni < NI; ni++) {
                    MMA_BF16(acc[mi][ni], ah[mi], bh[ni]);
                    MMA_BF16(acc[mi][ni], ah[mi], bl[ni]);
                    MMA_BF16(acc[mi][ni], al[mi], bh[ni]);
                }
        }
    };

    int st = 0;
    load_tile(0);
    store_tile(st);
    __syncthreads();
    for (int k0 = 0; k0 < KK; k0 += BK) {
        const bool has_next = (k0 + BK < KK);
        if (has_next) load_tile(k0 + BK);
        compute(st);
        if (has_next) {
            store_tile(st ^ 1);
            __syncthreads();
            st ^= 1;
        }
    }

#pragma unroll
    for (int mi = 0; mi < MI; mi++) {
#pragma unroll
        for (int ni = 0; ni < NI; ni++) {
            int r0 = block_m + wm + mi * 16 + g;
            int c0 = wn + ni * 8 + 2 * t;
            if (r0 < M)
                *(float2*)&C[(size_t)r0 * NN + c0] =
                    make_float2(acc[mi][ni][0], acc[mi][ni][1]);
            if (r0 + 8 < M)
                *(float2*)&C[(size_t)(r0 + 8) * NN + c0] =
                    make_float2(acc[mi][ni][2], acc[mi][ni][3]);
        }
    }
}

// ---------------- aggregation (one warp per dst node, 8-wide gather pipeline) ----------------
__global__ void agg128_relu_kernel(const float* __restrict__ bias) {
    const float* __restrict__ h = (const float*)g_h1;
    const int warp = blockIdx.x * (blockDim.x >> 5) + (threadIdx.x >> 5);
    const int lane = threadIdx.x & 31;
    if (warp >= N_NODES) return;

    const int start = g_rowptr[warp];
    const int end   = g_rowptr[warp + 1];

    float4 acc = make_float4(0.f, 0.f, 0.f, 0.f);
    for (int base = start; base < end; base += 32) {
        int e = base + lane;
        int s = 0; float nm = 0.f;
        if (e < end) { s = g_srcidx[e]; nm = g_norm[e]; }
        int cnt = min(32, end - base);
        int j = 0;
        for (; j + 8 <= cnt; j += 8) {
            int sv[8]; float nv[8]; float4 vv[8];
#pragma unroll
            for (int u = 0; u < 8; u++) {
                sv[u] = __shfl_sync(0xffffffffu, s, j + u);
                nv[u] = __shfl_sync(0xffffffffu, nm, j + u);
            }
#pragma unroll
            for (int u = 0; u < 8; u++)
                vv[u] = *(const float4*)&h[(size_t)sv[u] * C_HID + lane * 4];
#pragma unroll
            for (int u = 0; u < 8; u++) {
                acc.x += vv[u].x * nv[u];
                acc.y += vv[u].y * nv[u];
                acc.z += vv[u].z * nv[u];
                acc.w += vv[u].w * nv[u];
            }
        }
        for (; j < cnt; j++) {
            int   ss = __shfl_sync(0xffffffffu, s, j);
            float nn = __shfl_sync(0xffffffffu, nm, j);
            float4 v = *(const float4*)&h[(size_t)ss * C_HID + lane * 4];
            acc.x += v.x * nn; acc.y += v.y * nn;
            acc.z += v.z * nn; acc.w += v.w * nn;
        }
    }
    float dv = g_dinv[warp];
    float sn = dv * dv;
    float4 v = *(const float4*)&h[(size_t)warp * C_HID + lane * 4];
    acc.x += v.x * sn; acc.y += v.y * sn; acc.z += v.z * sn; acc.w += v.w * sn;
    const float4 b = *(const float4*)&bias[lane * 4];
    acc.x = fmaxf(acc.x + b.x, 0.f);
    acc.y = fmaxf(acc.y + b.y, 0.f);
    acc.z = fmaxf(acc.z + b.z, 0.f);
    acc.w = fmaxf(acc.w + b.w, 0.f);
    uint32_t h0, l0, h1, l1;
    split2(acc.x, acc.y, h0, l0);
    split2(acc.z, acc.w, h1, l1);
    size_t o = (size_t)warp * (C_HID / 2) + lane * 2;
    g_a1h[o]     = h0;
    g_a1h[o + 1] = h1;
    g_a1l[o]     = l0;
    g_a1l[o + 1] = l1;
}

__global__ void agg64_kernel(const float* __restrict__ bias,
                             float* __restrict__ out) {
    const float* __restrict__ h = (const float*)g_h2;
    const int warp = blockIdx.x * (blockDim.x >> 5) + (threadIdx.x >> 5);
    const int lane = threadIdx.x & 31;
    if (warp >= N_NODES) return;

    const int start = g_rowptr[warp];
    const int end   = g_rowptr[warp + 1];

    float2 acc = make_float2(0.f, 0.f);
    for (int base = start; base < end; base += 32) {
        int e = base + lane;
        int s = 0; float nm = 0.f;
        if (e < end) { s = g_srcidx[e]; nm = g_norm[e]; }
        int cnt = min(32, end - base);
        int j = 0;
        for (; j + 8 <= cnt; j += 8) {
            int sv[8]; float nv[8]; float2 vv[8];
#pragma unroll
            for (int u = 0; u < 8; u++) {
                sv[u] = __shfl_sync(0xffffffffu, s, j + u);
                nv[u] = __shfl_sync(0xffffffffu, nm, j + u);
            }
#pragma unroll
            for (int u = 0; u < 8; u++)
                vv[u] = *(const float2*)&h[(size_t)sv[u] * C_OUT + lane * 2];
#pragma unroll
            for (int u = 0; u < 8; u++) {
                acc.x += vv[u].x * nv[u];
                acc.y += vv[u].y * nv[u];
            }
        }
        for (; j < cnt; j++) {
            int   ss = __shfl_sync(0xffffffffu, s, j);
            float nn = __shfl_sync(0xffffffffu, nm, j);
            float2 v = *(const float2*)&h[(size_t)ss * C_OUT + lane * 2];
            acc.x += v.x * nn; acc.y += v.y * nn;
        }
    }
    float dv = g_dinv[warp];
    float sn = dv * dv;
    float2 v = *(const float2*)&h[(size_t)warp * C_OUT + lane * 2];
    acc.x += v.x * sn; acc.y += v.y * sn;
    const float2 b = *(const float2*)&bias[lane * 2];
    acc.x += b.x; acc.y += b.y;
    *(float2*)&out[(size_t)warp * C_OUT + lane * 2] = acc;
}

// ---------------- launch (single linear stream) ----------------
extern "C" void kernel_launch(void* const* d_in, const int* in_sizes, int n_in,
                              void* d_out, int out_size) {
    const float* x  = (const float*)d_in[0];
    const void*  ei = d_in[1];
    const float* W1 = (const float*)d_in[2];
    const float* b1 = (const float*)d_in[3];
    const float* W2 = (const float*)d_in[4];
    const float* b2 = (const float*)d_in[5];
    float* out = (float*)d_out;

    const int TB = 256;
    const int nodeBlocks = (N_NODES + TB - 1) / TB;
    const int edgeBlocks = (N_EDGES + TB - 1) / TB;

    detect_dtype_kernel<<<1, 1>>>(ei);
    wprep_kernel<0><<<(C_HID * C_IN / 2 + TB - 1) / TB, TB>>>(W1);
    wprep_kernel<1><<<(C_OUT * C_HID / 2 + TB - 1) / TB, TB>>>(W2);

    // layer 1 GEMM: g_h1 = x @ W1
    {
        constexpr int BM = 64;
        constexpr int SMEM = 4 * 20 * (BM + 128) * 4;
        auto kfn = mma_gemm_kernel<BM, 128, 2, 4, C_HID, C_IN, 0>;
        cudaFuncSetAttribute(kfn, cudaFuncAttributeMaxDynamicSharedMemorySize, SMEM);
        int grid = (N_NODES + BM - 1) / BM;
        kfn<<<grid, 256, SMEM>>>(x, N_NODES);
    }
    zero_cnt_kernel<<<nodeBlocks, TB>>>();
    count_kernel<<<edgeBlocks, TB>>>(ei);
    scan1_kernel<<<SCAN_NB, SCAN_TB>>>();       // also computes dinv
    scan2_kernel<<<1, SCAN_TB>>>();
    scan3_kernel<<<SCAN_NB, SCAN_TB>>>();
    scatter_kernel<<<edgeBlocks, TB>>>(ei);

    // a1 = relu(aggregate(h1) + b1)  -> bf16 hi/lo pairs
    {
        const int WPB = 8;
        int grid = (N_NODES + WPB - 1) / WPB;
        agg128_relu_kernel<<<grid, WPB * 32>>>(b1);
    }
    // layer 2 GEMM: g_h2 = a1 @ W2
    {
        constexpr int BM = 64;
        constexpr int SMEM = 4 * 20 * (BM + 64) * 4;
        auto kfn = mma_gemm_kernel<BM, 64, 2, 4, C_OUT, C_HID, 1>;
        cudaFuncSetAttribute(kfn, cudaFuncAttributeMaxDynamicSharedMemorySize, SMEM);
        int grid = (N_NODES + BM - 1) / BM;
        kfn<<<grid, 256, SMEM>>>(nullptr, N_NODES);
    }
    // out = aggregate(h2) + b2
    {
        const int WPB = 8;
        int grid = (N_NODES + WPB - 1) / WPB;
        agg64_kernel<<<grid, WPB * 32>>>(b2, out);
    }
}

// round 17
// speedup vs baseline: 1.3452x; 1.0144x over previous
#include <cuda_runtime.h>
#include <cuda_bf16.h>
#include <stdint.h>

#define N_NODES 50000
#define N_EDGES 800000
#define C_IN    256
#define C_HID   128
#define C_OUT   64

#define SCAN_TB 256
#define SCAN_NB ((N_NODES + SCAN_TB - 1) / SCAN_TB)   // 196

// ---------------- scratch (static device globals; no allocation) ----------------
// RULE (learned R1/R7): never pass these as kernel arguments from host code.
// RULE (learned R12): tcgen05 is NOT compilable in this harness (plain compute_103).
// RULE (learned R14): keep the launch sequence a single linear stream.
__device__ int   g_is64;
__device__ int   g_cnt[N_NODES];
__device__ float g_dinv[N_NODES];
__device__ int   g_rowptr[N_NODES + 1];
__device__ int   g_fill[N_NODES];
__device__ int   g_srcidx[N_EDGES];
__device__ float g_norm[N_EDGES];
__device__ int   g_bsum[SCAN_NB];
__device__ int   g_boff[SCAN_NB];
__device__ float g_h1[(size_t)N_NODES * C_HID];
__device__ float g_h2[(size_t)N_NODES * C_OUT];
__device__ uint32_t g_a1h[(size_t)N_NODES * (C_HID / 2)];
__device__ uint32_t g_a1l[(size_t)N_NODES * (C_HID / 2)];
__device__ uint32_t g_w1h[C_HID * (C_IN / 2)];
__device__ uint32_t g_w1l[C_HID * (C_IN / 2)];
__device__ uint32_t g_w2h[C_OUT * (C_HID / 2)];
__device__ uint32_t g_w2l[C_OUT * (C_HID / 2)];

// ---------------- helpers ----------------
__device__ __forceinline__ uint32_t packbf2(float x, float y) {
    __nv_bfloat162 v = __floats2bfloat162_rn(x, y);
    return *(uint32_t*)&v;
}
__device__ __forceinline__ void split2(float x, float y, uint32_t& hi, uint32_t& lo) {
    __nv_bfloat16 hx = __float2bfloat16_rn(x);
    __nv_bfloat16 hy = __float2bfloat16_rn(y);
    __nv_bfloat162 h = __halves2bfloat162(hx, hy);
    hi = *(uint32_t*)&h;
    lo = packbf2(x - __bfloat162float(hx), y - __bfloat162float(hy));
}
__device__ __forceinline__ uint32_t smem_u32(const void* p) {
    uint32_t a;
    asm("{ .reg .u64 t; cvta.to.shared.u64 t, %1; cvt.u32.u64 %0, t; }" : "=r"(a) : "l"(p));
    return a;
}
__device__ __forceinline__ void ldsm4(uint32_t& r0, uint32_t& r1, uint32_t& r2,
                                      uint32_t& r3, uint32_t addr) {
    asm volatile("ldmatrix.sync.aligned.m8n8.x4.shared.b16 {%0,%1,%2,%3}, [%4];"
                 : "=r"(r0), "=r"(r1), "=r"(r2), "=r"(r3) : "r"(addr));
}

#define MMA_BF16(c, a, b)                                                     \
    asm volatile(                                                             \
        "mma.sync.aligned.m16n8k16.row.col.f32.bf16.bf16.f32 "                \
        "{%0,%1,%2,%3},{%4,%5,%6,%7},{%8,%9},{%0,%1,%2,%3};"                  \
        : "+f"((c)[0]), "+f"((c)[1]), "+f"((c)[2]), "+f"((c)[3])              \
        : "r"((a)[0]), "r"((a)[1]), "r"((a)[2]), "r"((a)[3]),                 \
          "r"((b)[0]), "r"((b)[1]))

// ---------------- edge dtype detection ----------------
__global__ void detect_dtype_kernel(const void* ei) {
    const long long* e64 = (const long long*)ei;
    bool ok = true;
    for (int i = 0; i < 8; i++) {
        long long s = e64[i];
        long long d = e64[N_EDGES + i];
        if (s < 0 || s >= N_NODES || d < 0 || d >= N_NODES) ok = false;
    }
    g_is64 = ok ? 1 : 0;
}

__device__ __forceinline__ int edge_at(const void* ei, size_t idx, int is64) {
    long long v;
    if (is64) v = ((const long long*)ei)[idx];
    else      v = (long long)((const int*)ei)[idx];
    v = v < 0 ? 0 : (v >= N_NODES ? N_NODES - 1 : v);
    return (int)v;
}

// ---------------- weight prep ----------------
template <int LAYER>
__global__ void wprep_kernel(const float* __restrict__ W) {
    constexpr int K = (LAYER == 0) ? C_IN  : C_HID;
    constexpr int N = (LAYER == 0) ? C_HID : C_OUT;
    uint32_t* __restrict__ Wh = (LAYER == 0) ? g_w1h : g_w2h;
    uint32_t* __restrict__ Wl = (LAYER == 0) ? g_w1l : g_w2l;
    int idx = blockIdx.x * blockDim.x + threadIdx.x;
    if (idx >= N * (K / 2)) return;
    int n  = idx / (K / 2);
    int kp = idx % (K / 2);
    float f0 = W[(size_t)(2 * kp) * N + n];
    float f1 = W[(size_t)(2 * kp + 1) * N + n];
    uint32_t hi, lo;
    split2(f0, f1, hi, lo);
    Wh[idx] = hi;
    Wl[idx] = lo;
}

// ---------------- CSR build ----------------
__global__ void zero_cnt_kernel() {
    int i = blockIdx.x * blockDim.x + threadIdx.x;
    if (i < N_NODES) g_cnt[i] = 0;
}

__global__ void count_kernel(const void* __restrict__ ei) {
    int e = blockIdx.x * blockDim.x + threadIdx.x;
    if (e < N_EDGES) {
        int d = edge_at(ei, (size_t)N_EDGES + e, g_is64);
        atomicAdd(&g_cnt[d], 1);
    }
}

// scan1 also computes dinv (same dependency: final g_cnt)
__global__ void scan1_kernel() {
    __shared__ int sm[SCAN_TB];
    int i = blockIdx.x * SCAN_TB + threadIdx.x;
    int c = (i < N_NODES) ? g_cnt[i] : 0;
    sm[threadIdx.x] = c;
    if (i < N_NODES) g_dinv[i] = rsqrtf((float)c + 1.0f);
    __syncthreads();
#pragma unroll
    for (int off = SCAN_TB / 2; off > 0; off >>= 1) {
        if (threadIdx.x < off) sm[threadIdx.x] += sm[threadIdx.x + off];
        __syncthreads();
    }
    if (threadIdx.x == 0) g_bsum[blockIdx.x] = sm[0];
}

__global__ void scan2_kernel() {
    __shared__ int sm[SCAN_TB];
    int tid = threadIdx.x;
    sm[tid] = (tid < SCAN_NB) ? g_bsum[tid] : 0;
    __syncthreads();
#pragma unroll
    for (int off = 1; off < SCAN_TB; off <<= 1) {
        int v = 0;
        if (tid >= off) v = sm[tid - off];
        __syncthreads();
        if (tid >= off) sm[tid] += v;
        __syncthreads();
    }
    if (tid < SCAN_NB) g_boff[tid] = (tid == 0) ? 0 : sm[tid - 1];
}

__global__ void scan3_kernel() {
    __shared__ int sm[SCAN_TB];
    int tid = threadIdx.x;
    int i = blockIdx.x * SCAN_TB + tid;
    sm[tid] = (i < N_NODES) ? g_cnt[i] : 0;
    __syncthreads();
#pragma unroll
    for (int off = 1; off < SCAN_TB; off <<= 1) {
        int v = 0;
        if (tid >= off) v = sm[tid - off];
        __syncthreads();
        if (tid >= off) sm[tid] += v;
        __syncthreads();
    }
    if (i < N_NODES) {
        int excl = ((tid == 0) ? 0 : sm[tid - 1]) + g_boff[blockIdx.x];
        g_rowptr[i] = excl;
        g_fill[i]   = excl;
    }
    if (blockIdx.x == 0 && tid == 0) g_rowptr[N_NODES] = N_EDGES;
}

__global__ void scatter_kernel(const void* __restrict__ ei) {
    int e = blockIdx.x * blockDim.x + threadIdx.x;
    if (e < N_EDGES) {
        int is64 = g_is64;
        int s = edge_at(ei, e, is64);
        int d = edge_at(ei, (size_t)N_EDGES + e, is64);
        int p = atomicAdd(&g_fill[d], 1);
        g_srcidx[p] = s;
        g_norm[p]   = g_dinv[s] * g_dinv[d];
    }
}

// ---------------- bf16x3 tensor-core GEMM, double-buffered + ldmatrix, vector fills ----------------
template <int BM, int BN, int WARPS_M, int WARPS_N, int NN, int KK, int LAYER>
__global__ void __launch_bounds__(256)
mma_gemm_kernel(const float* __restrict__ A_ext, int M) {
    constexpr int BK  = 32;
    constexpr int KP  = BK / 2;       // 16 u32 per row
    constexpr int KPP = KP + 4;       // 80B stride: 8-row groups bank-disjoint for LDSM
    constexpr int WM = BM / WARPS_M, WN = BN / WARPS_N;
    constexpr int MI = WM / 16, NI = WN / 8;
    static_assert(NI % 2 == 0, "NI must be even for paired B ldmatrix");
    constexpr int ALD0 = BM * (BK / 4) / 256;   // float4 per thread (layer-0 A)
    constexpr int AQ4  = BM * 4 / 256;          // uint4 per thread (layer-1 A pairs)
    constexpr int BQ4  = BN * 4 / 256;          // uint4 per thread (B pairs)
    constexpr int ASZ = BM * KPP;
    constexpr int BSZ = BN * KPP;

    extern __shared__ uint32_t smp[];
    uint32_t* Ah = smp;
    uint32_t* Al = Ah + 2 * ASZ;
    uint32_t* Bh = Al + 2 * ASZ;
    uint32_t* Bl = Bh + 2 * BSZ;

    const uint32_t sm_base = smem_u32(smp);

    const uint32_t* __restrict__ WhG = (LAYER == 0) ? g_w1h : g_w2h;
    const uint32_t* __restrict__ WlG = (LAYER == 0) ? g_w1l : g_w2l;
    float* __restrict__ C = (LAYER == 0) ? (float*)g_h1 : (float*)g_h2;

    const int tid  = threadIdx.x;
    const int wid  = tid >> 5;
    const int lane = tid & 31;
    const int g    = lane >> 2;
    const int t    = lane & 3;
    const int wm   = (wid / WARPS_N) * WM;
    const int wn   = (wid % WARPS_N) * WN;
    const int block_m = blockIdx.x * BM;

    float4 ra0[ALD0 > 0 ? ALD0 : 1];
    uint4  ra1h[AQ4 > 0 ? AQ4 : 1], ra1l[AQ4 > 0 ? AQ4 : 1];
    uint4  rbh[BQ4 > 0 ? BQ4 : 1], rbl[BQ4 > 0 ? BQ4 : 1];

    float acc[MI][NI][4];
#pragma unroll
    for (int mi = 0; mi < MI; mi++)
#pragma unroll
        for (int ni = 0; ni < NI; ni++)
#pragma unroll
            for (int j = 0; j < 4; j++) acc[mi][ni][j] = 0.0f;

    auto load_tile = [&](int k0) {
        if (LAYER == 0) {
#pragma unroll
            for (int u = 0; u < ALD0; u++) {
                int i = u * 256 + tid;
                int row = i / (BK / 4);
                int c4  = i % (BK / 4);
                int gm  = block_m + row;
                ra0[u] = (gm < M) ? *(const float4*)&A_ext[(size_t)gm * KK + k0 + c4 * 4]
                                  : make_float4(0.f, 0.f, 0.f, 0.f);
            }
        } else {
#pragma unroll
            for (int u = 0; u < AQ4; u++) {
                int i = u * 256 + tid;     // over BM*4 uint4 slots
                int row = i >> 2;
                int q4  = i & 3;
                int gm  = block_m + row;
                if (gm < M) {
                    size_t o = (size_t)gm * (KK / 2) + k0 / 2 + q4 * 4;
                    ra1h[u] = *(const uint4*)&g_a1h[o];
                    ra1l[u] = *(const uint4*)&g_a1l[o];
                } else {
                    ra1h[u] = make_uint4(0, 0, 0, 0);
                    ra1l[u] = make_uint4(0, 0, 0, 0);
                }
            }
        }
#pragma unroll
        for (int u = 0; u < BQ4; u++) {
            int i = u * 256 + tid;         // over BN*4 uint4 slots
            int n  = i >> 2;
            int q4 = i & 3;
            size_t o = (size_t)n * (KK / 2) + k0 / 2 + q4 * 4;
            rbh[u] = *(const uint4*)&WhG[o];
            rbl[u] = *(const uint4*)&WlG[o];
        }
    };

    auto store_tile = [&](int st) {
        uint32_t* ah = Ah + st * ASZ;
        uint32_t* al = Al + st * ASZ;
        uint32_t* bh = Bh + st * BSZ;
        uint32_t* bl = Bl + st * BSZ;
        if (LAYER == 0) {
#pragma unroll
            for (int u = 0; u < ALD0; u++) {
                int i = u * 256 + tid;
                int row = i / (BK / 4);
                int c4  = i % (BK / 4);
                uint32_t h0, l0, h1, l1;
                split2(ra0[u].x, ra0[u].y, h0, l0);
                split2(ra0[u].z, ra0[u].w, h1, l1);
                *(uint2*)&ah[row * KPP + c4 * 2] = make_uint2(h0, h1);
                *(uint2*)&al[row * KPP + c4 * 2] = make_uint2(l0, l1);
            }
        } else {
#pragma unroll
            for (int u = 0; u < AQ4; u++) {
                int i = u * 256 + tid;
                int row = i >> 2;
                int q4  = i & 3;
                *(uint4*)&ah[row * KPP + q4 * 4] = ra1h[u];
                *(uint4*)&al[row * KPP + q4 * 4] = ra1l[u];
            }
        }
#pragma unroll
        for (int u = 0; u < BQ4; u++) {
            int i = u * 256 + tid;
            int n  = i >> 2;
            int q4 = i & 3;
            *(uint4*)&bh[n * KPP + q4 * 4] = rbh[u];
            *(uint4*)&bl[n * KPP + q4 * 4] = rbl[u];
        }
    };

    auto compute = [&](int st) {
        const uint32_t baseAh = sm_base + (uint32_t)(st * ASZ) * 4u;
        const uint32_t baseAl = sm_base + (uint32_t)((2 + st) * ASZ) * 4u;
        const uint32_t baseBh = sm_base + (uint32_t)(4 * ASZ + st * BSZ) * 4u;
        const uint32_t baseBl = sm_base + (uint32_t)(4 * ASZ + (2 + st) * BSZ) * 4u;
        const int arow = lane & 15;
        const int ahalf = (lane >> 4) << 2;
        const int q = lane >> 3;
        const int brow = lane & 7;
#pragma unroll
        for (int s = 0; s < 2; s++) {
            const int sp = s * 8;
            uint32_t ah[MI][4], al[MI][4];
#pragma unroll
            for (int mi = 0; mi < MI; mi++) {
                uint32_t offA = (uint32_t)((wm + mi * 16 + arow) * KPP + sp + ahalf) * 4u;
                ldsm4(ah[mi][0], ah[mi][1], ah[mi][2], ah[mi][3], baseAh + offA);
                ldsm4(al[mi][0], al[mi][1], al[mi][2], al[mi][3], baseAl + offA);
            }
            uint32_t bh[NI][2], bl[NI][2];
#pragma unroll
            for (int p = 0; p < NI / 2; p++) {
                uint32_t offB = (uint32_t)((wn + ((p << 1) + (q >> 1)) * 8 + brow) * KPP
                                           + sp + ((q & 1) << 2)) * 4u;
                ldsm4(bh[2 * p][0], bh[2 * p][1], bh[2 * p + 1][0], bh[2 * p + 1][1],
                      baseBh + offB);
                ldsm4(bl[2 * p][0], bl[2 * p][1], bl[2 * p + 1][0], bl[2 * p + 1][1],
                      baseBl + offB);
            }
#pragma unroll
            for (int mi = 0; mi < MI; mi++)
#pragma unroll
                for (int ni = 0; ni < NI; ni++) {
                    MMA_BF16(acc[mi][ni], ah[mi], bh[ni]);
                    MMA_BF16(acc[mi][ni], ah[mi], bl[ni]);
                    MMA_BF16(acc[mi][ni], al[mi], bh[ni]);
                }
        }
    };

    int st = 0;
    load_tile(0);
    store_tile(st);
    __syncthreads();
    for (int k0 = 0; k0 < KK; k0 += BK) {
        const bool has_next = (k0 + BK < KK);
        if (has_next) load_tile(k0 + BK);
        compute(st);
        if (has_next) {
            store_tile(st ^ 1);
            __syncthreads();
            st ^= 1;
        }
    }

#pragma unroll
    for (int mi = 0; mi < MI; mi++) {
#pragma unroll
        for (int ni = 0; ni < NI; ni++) {
            int r0 = block_m + wm + mi * 16 + g;
            int c0 = wn + ni * 8 + 2 * t;
            if (r0 < M)
                *(float2*)&C[(size_t)r0 * NN + c0] =
                    make_float2(acc[mi][ni][0], acc[mi][ni][1]);
            if (r0 + 8 < M)
                *(float2*)&C[(size_t)(r0 + 8) * NN + c0] =
                    make_float2(acc[mi][ni][2], acc[mi][ni][3]);
        }
    }
}

// ---------------- aggregation (one warp per dst node, 8-wide gather pipeline) ----------------
__global__ void agg128_relu_kernel(const float* __restrict__ bias) {
    const float* __restrict__ h = (const float*)g_h1;
    const int warp = blockIdx.x * (blockDim.x >> 5) + (threadIdx.x >> 5);
    const int lane = threadIdx.x & 31;
    if (warp >= N_NODES) return;

    const int start = g_rowptr[warp];
    const int end   = g_rowptr[warp + 1];

    float4 acc = make_float4(0.f, 0.f, 0.f, 0.f);
    for (int base = start; base < end; base += 32) {
        int e = base + lane;
        int s = 0; float nm = 0.f;
        if (e < end) { s = g_srcidx[e]; nm = g_norm[e]; }
        int cnt = min(32, end - base);
        int j = 0;
        for (; j + 8 <= cnt; j += 8) {
            int sv[8]; float nv[8]; float4 vv[8];
#pragma unroll
            for (int u = 0; u < 8; u++) {
                sv[u] = __shfl_sync(0xffffffffu, s, j + u);
                nv[u] = __shfl_sync(0xffffffffu, nm, j + u);
            }
#pragma unroll
            for (int u = 0; u < 8; u++)
                vv[u] = *(const float4*)&h[(size_t)sv[u] * C_HID + lane * 4];
#pragma unroll
            for (int u = 0; u < 8; u++) {
                acc.x += vv[u].x * nv[u];
                acc.y += vv[u].y * nv[u];
                acc.z += vv[u].z * nv[u];
                acc.w += vv[u].w * nv[u];
            }
        }
        for (; j < cnt; j++) {
            int   ss = __shfl_sync(0xffffffffu, s, j);
            float nn = __shfl_sync(0xffffffffu, nm, j);
            float4 v = *(const float4*)&h[(size_t)ss * C_HID + lane * 4];
            acc.x += v.x * nn; acc.y += v.y * nn;
            acc.z += v.z * nn; acc.w += v.w * nn;
        }
    }
    float dv = g_dinv[warp];
    float sn = dv * dv;
    float4 v = *(const float4*)&h[(size_t)warp * C_HID + lane * 4];
    acc.x += v.x * sn; acc.y += v.y * sn; acc.z += v.z * sn; acc.w += v.w * sn;
    const float4 b = *(const float4*)&bias[lane * 4];
    acc.x = fmaxf(acc.x + b.x, 0.f);
    acc.y = fmaxf(acc.y + b.y, 0.f);
    acc.z = fmaxf(acc.z + b.z, 0.f);
    acc.w = fmaxf(acc.w + b.w, 0.f);
    uint32_t h0, l0, h1, l1;
    split2(acc.x, acc.y, h0, l0);
    split2(acc.z, acc.w, h1, l1);
    size_t o = (size_t)warp * (C_HID / 2) + lane * 2;
    g_a1h[o]     = h0;
    g_a1h[o + 1] = h1;
    g_a1l[o]     = l0;
    g_a1l[o + 1] = l1;
}

__global__ void agg64_kernel(const float* __restrict__ bias,
                             float* __restrict__ out) {
    const float* __restrict__ h = (const float*)g_h2;
    const int warp = blockIdx.x * (blockDim.x >> 5) + (threadIdx.x >> 5);
    const int lane = threadIdx.x & 31;
    if (warp >= N_NODES) return;

    const int start = g_rowptr[warp];
    const int end   = g_rowptr[warp + 1];

    float2 acc = make_float2(0.f, 0.f);
    for (int base = start; base < end; base += 32) {
        int e = base + lane;
        int s = 0; float nm = 0.f;
        if (e < end) { s = g_srcidx[e]; nm = g_norm[e]; }
        int cnt = min(32, end - base);
        int j = 0;
        for (; j + 8 <= cnt; j += 8) {
            int sv[8]; float nv[8]; float2 vv[8];
#pragma unroll
            for (int u = 0; u < 8; u++) {
                sv[u] = __shfl_sync(0xffffffffu, s, j + u);
                nv[u] = __shfl_sync(0xffffffffu, nm, j + u);
            }
#pragma unroll
            for (int u = 0; u < 8; u++)
                vv[u] = *(const float2*)&h[(size_t)sv[u] * C_OUT + lane * 2];
#pragma unroll
            for (int u = 0; u < 8; u++) {
                acc.x += vv[u].x * nv[u];
                acc.y += vv[u].y * nv[u];
            }
        }
        for (; j < cnt; j++) {
            int   ss = __shfl_sync(0xffffffffu, s, j);
            float nn = __shfl_sync(0xffffffffu, nm, j);
            float2 v = *(const float2*)&h[(size_t)ss * C_OUT + lane * 2];
            acc.x += v.x * nn; acc.y += v.y * nn;
        }
    }
    float dv = g_dinv[warp];
    float sn = dv * dv;
    float2 v = *(const float2*)&h[(size_t)warp * C_OUT + lane * 2];
    acc.x += v.x * sn; acc.y += v.y * sn;
    const float2 b = *(const float2*)&bias[lane * 2];
    acc.x += b.x; acc.y += b.y;
    *(float2*)&out[(size_t)warp * C_OUT + lane * 2] = acc;
}

// ---------------- launch (single linear stream) ----------------
extern "C" void kernel_launch(void* const* d_in, const int* in_sizes, int n_in,
                              void* d_out, int out_size) {
    const float* x  = (const float*)d_in[0];
    const void*  ei = d_in[1];
    const float* W1 = (const float*)d_in[2];
    const float* b1 = (const float*)d_in[3];
    const float* W2 = (const float*)d_in[4];
    const float* b2 = (const float*)d_in[5];
    float* out = (float*)d_out;

    const int TB = 256;
    const int nodeBlocks = (N_NODES + TB - 1) / TB;
    const int edgeBlocks = (N_EDGES + TB - 1) / TB;

    detect_dtype_kernel<<<1, 1>>>(ei);
    wprep_kernel<0><<<(C_HID * C_IN / 2 + TB - 1) / TB, TB>>>(W1);
    wprep_kernel<1><<<(C_OUT * C_HID / 2 + TB - 1) / TB, TB>>>(W2);

    // layer 1 GEMM: g_h1 = x @ W1
    {
        constexpr int BM = 64;
        constexpr int SMEM = 4 * 20 * (BM + 128) * 4;
        auto kfn = mma_gemm_kernel<BM, 128, 2, 4, C_HID, C_IN, 0>;
        cudaFuncSetAttribute(kfn, cudaFuncAttributeMaxDynamicSharedMemorySize, SMEM);
        int grid = (N_NODES + BM - 1) / BM;
        kfn<<<grid, 256, SMEM>>>(x, N_NODES);
    }
    zero_cnt_kernel<<<nodeBlocks, TB>>>();
    count_kernel<<<edgeBlocks, TB>>>(ei);
    scan1_kernel<<<SCAN_NB, SCAN_TB>>>();       // also computes dinv
    scan2_kernel<<<1, SCAN_TB>>>();
    scan3_kernel<<<SCAN_NB, SCAN_TB>>>();
    scatter_kernel<<<edgeBlocks, TB>>>(ei);

    // a1 = relu(aggregate(h1) + b1)  -> bf16 hi/lo pairs
    {
        const int WPB = 8;
        int grid = (N_NODES + WPB - 1) / WPB;
        agg128_relu_kernel<<<grid, WPB * 32>>>(b1);
    }
    // layer 2 GEMM: g_h2 = a1 @ W2
    {
        constexpr int BM = 64;
        constexpr int SMEM = 4 * 20 * (BM + 64) * 4;
        auto kfn = mma_gemm_kernel<BM, 64, 2, 4, C_OUT, C_HID, 1>;
        cudaFuncSetAttribute(kfn, cudaFuncAttributeMaxDynamicSharedMemorySize, SMEM);
        int grid = (N_NODES + BM - 1) / BM;
        kfn<<<grid, 256, SMEM>>>(nullptr, N_NODES);
    }
    // out = aggregate(h2) + b2
    {
        const int WPB = 8;
        int grid = (N_NODES + WPB - 1) / WPB;
        agg64_kernel<<<grid, WPB * 32>>>(b2, out);
    }
}